// round 1
// baseline (speedup 1.0000x reference)
#include <cuda_runtime.h>
#include <cstdint>

// Suffix (reverse cumulative) max along last dim.
// Input: (8, 1, 2048, 2048) fp32 -> 16384 rows x 2048 cols.
// One CTA per row, 256 threads, 8 elements/thread via 2x float4.

#define ROW_LEN   2048
#define THREADS   256
#define ELEMS_PT  8      // ROW_LEN / THREADS

__device__ __forceinline__ float neg_inf() {
    return __int_as_float(0xff800000);
}

__global__ void __launch_bounds__(THREADS, 8)
suffix_max_kernel(const float* __restrict__ in, float* __restrict__ out) {
    const size_t row_off = (size_t)blockIdx.x * ROW_LEN;
    const float4* __restrict__ rin  = reinterpret_cast<const float4*>(in  + row_off);
    float4* __restrict__       rout = reinterpret_cast<float4*>(out + row_off);

    const int t    = threadIdx.x;
    const int lane = t & 31;
    const int warp = t >> 5;

    // ---- load 8 contiguous floats (2x float4) ----
    float4 a = rin[t * 2 + 0];
    float4 b = rin[t * 2 + 1];
    float v0 = a.x, v1 = a.y, v2 = a.z, v3 = a.w;
    float v4 = b.x, v5 = b.y, v6 = b.z, v7 = b.w;

    // ---- suffix max within the 8-element chunk ----
    v6 = fmaxf(v6, v7);
    v5 = fmaxf(v5, v6);
    v4 = fmaxf(v4, v5);
    v3 = fmaxf(v3, v4);
    v2 = fmaxf(v2, v3);
    v1 = fmaxf(v1, v2);
    v0 = fmaxf(v0, v1);
    const float chunk_max = v0;

    // ---- warp-level inclusive suffix scan of chunk maxima ----
    float incl = chunk_max;
    #pragma unroll
    for (int off = 1; off < 32; off <<= 1) {
        float x = __shfl_down_sync(0xffffffffu, incl, off);
        if (lane + off < 32) incl = fmaxf(incl, x);
    }
    // exclusive carry from lanes to the right within this warp
    float lane_excl = __shfl_down_sync(0xffffffffu, incl, 1);
    if (lane == 31) lane_excl = neg_inf();

    // ---- cross-warp suffix scan (8 warps) ----
    __shared__ float warp_max[8];
    if (lane == 0) warp_max[warp] = incl;   // incl at lane 0 == warp's max
    __syncthreads();

    __shared__ float warp_carry[8];         // max over warps (w+1 .. 7)
    if (t < 8) {
        float wv = warp_max[t];
        // suffix scan over 8 values using shuffles within the first warp
        float s = wv;
        #pragma unroll
        for (int off = 1; off < 8; off <<= 1) {
            float x = __shfl_down_sync(0x000000ffu, s, off);
            if (t + off < 8) s = fmaxf(s, x);
        }
        // exclusive: carry from warps strictly to the right
        float e = __shfl_down_sync(0x000000ffu, s, 1);
        if (t == 7) e = neg_inf();
        warp_carry[t] = e;
    }
    __syncthreads();

    // ---- total exclusive carry for this thread ----
    const float carry = fmaxf(lane_excl, warp_carry[warp]);

    v0 = fmaxf(v0, carry);
    v1 = fmaxf(v1, carry);
    v2 = fmaxf(v2, carry);
    v3 = fmaxf(v3, carry);
    v4 = fmaxf(v4, carry);
    v5 = fmaxf(v5, carry);
    v6 = fmaxf(v6, carry);
    v7 = fmaxf(v7, carry);

    rout[t * 2 + 0] = make_float4(v0, v1, v2, v3);
    rout[t * 2 + 1] = make_float4(v4, v5, v6, v7);
}

extern "C" void kernel_launch(void* const* d_in, const int* in_sizes, int n_in,
                              void* d_out, int out_size) {
    const float* x = (const float*)d_in[0];
    float* out = (float*)d_out;
    const int n_rows = out_size / ROW_LEN;   // 16384
    suffix_max_kernel<<<n_rows, THREADS>>>(x, out);
}